// round 14
// baseline (speedup 1.0000x reference)
#include <cuda_runtime.h>
#include <cuda_bf16.h>
#include <math.h>
#include <stdint.h>

// Problem constants
#define B_    4
#define T_    2048
#define C_    2048
#define H_    16
#define D_    128
#define NQKV_ 6144
#define MROWS 8192

// ---------------------------------------------------------------------------
// Scratch (device globals — no allocations allowed)
// ---------------------------------------------------------------------------
__device__ __align__(256) float g_Q[(size_t)B_ * H_ * T_ * D_];
__device__ __align__(256) float g_K[(size_t)B_ * H_ * T_ * D_];
__device__ __align__(256) float g_V[(size_t)B_ * H_ * T_ * D_];
__device__ __align__(256) float g_Y[(size_t)B_ * T_ * C_];
__device__ __align__(256) float g_cos[T_ * 64];
__device__ __align__(256) float g_sin[T_ * 64];
// per-row / per-column quantization scales (absmax)
__device__ float g_sxa[MROWS];   // x rows
__device__ float g_sy[MROWS];    // Y rows
__device__ float g_swa[NQKV_];   // w_attn columns
__device__ float g_swp[C_];      // w_proj columns
// int8 15-bit two-digit operands ([row][k] K-major, K = 2048)
__device__ __align__(256) char g_xd1[(size_t)MROWS * C_];
__device__ __align__(256) char g_xd2[(size_t)MROWS * C_];
__device__ __align__(256) char g_wad1[(size_t)NQKV_ * C_];  // w_attn^T
__device__ __align__(256) char g_wad2[(size_t)NQKV_ * C_];
__device__ __align__(256) char g_wpd1[(size_t)C_ * C_];     // w_proj^T
__device__ __align__(256) char g_wpd2[(size_t)C_ * C_];
__device__ __align__(256) char g_Yd1[(size_t)MROWS * C_];
__device__ __align__(256) char g_Yd2[(size_t)MROWS * C_];

#define QMAX 32511.0f   // 127*256 + 127

// ---------------------------------------------------------------------------
// helpers
// ---------------------------------------------------------------------------
__device__ __forceinline__ uint32_t smem_u32(const void* p) {
    uint32_t a;
    asm("{ .reg .u64 t; cvta.to.shared.u64 t, %1; cvt.u32.u64 %0, t; }" : "=r"(a) : "l"(p));
    return a;
}

#define CP_ASYNC16(dst, src) \
    asm volatile("cp.async.cg.shared.global [%0], [%1], 16;" :: "r"(dst), "l"(src) : "memory")
#define CP_COMMIT() asm volatile("cp.async.commit_group;" ::: "memory")
#define CP_WAIT1()  asm volatile("cp.async.wait_group 1;" ::: "memory")
#define CP_WAIT0()  asm volatile("cp.async.wait_group 0;" ::: "memory")

__device__ __forceinline__ void split_pair(float x0, float x1, unsigned& h, unsigned& l) {
    __nv_bfloat16 h0 = __float2bfloat16_rn(x0);
    __nv_bfloat16 h1 = __float2bfloat16_rn(x1);
    __nv_bfloat16 l0 = __float2bfloat16_rn(x0 - __bfloat162float(h0));
    __nv_bfloat16 l1 = __float2bfloat16_rn(x1 - __bfloat162float(h1));
    __nv_bfloat162 hh = __halves2bfloat162(h0, h1);
    __nv_bfloat162 ll = __halves2bfloat162(l0, l1);
    h = *reinterpret_cast<unsigned*>(&hh);
    l = *reinterpret_cast<unsigned*>(&ll);
}

__device__ __forceinline__ void mma_bf16(float c[4], const unsigned a[4], const unsigned b[2]) {
    asm volatile(
        "mma.sync.aligned.m16n8k16.row.col.f32.bf16.bf16.f32 "
        "{%0,%1,%2,%3}, {%4,%5,%6,%7}, {%8,%9}, {%0,%1,%2,%3};"
        : "+f"(c[0]), "+f"(c[1]), "+f"(c[2]), "+f"(c[3])
        : "r"(a[0]), "r"(a[1]), "r"(a[2]), "r"(a[3]), "r"(b[0]), "r"(b[1]));
}
__device__ __forceinline__ void mma_3x(float c[4],
                                       const unsigned ah[4], const unsigned al[4],
                                       const unsigned bh[2], const unsigned bl[2]) {
    mma_bf16(c, ah, bl);
    mma_bf16(c, al, bh);
    mma_bf16(c, ah, bh);
}

__device__ __forceinline__ void imma_s8(int c[4], const unsigned a[4], const unsigned b[2]) {
    asm volatile(
        "mma.sync.aligned.m16n8k32.row.col.s32.s8.s8.s32 "
        "{%0,%1,%2,%3}, {%4,%5,%6,%7}, {%8,%9}, {%0,%1,%2,%3};"
        : "+r"(c[0]), "+r"(c[1]), "+r"(c[2]), "+r"(c[3])
        : "r"(a[0]), "r"(a[1]), "r"(a[2]), "r"(a[3]), "r"(b[0]), "r"(b[1]));
}

__device__ __forceinline__ void quant15(float v, float inv_s, int& d1, int& d2) {
    int i = __float2int_rn(v * inv_s);
    i = max(-32511, min(32511, i));
    d1 = (i + 128) >> 8;
    d2 = i - (d1 << 8);
}

// ---------------------------------------------------------------------------
// Scale kernels (per-row for activations, per-column for weights)
// ---------------------------------------------------------------------------
__global__ void zero_colmax_kernel() {
    int i = blockIdx.x * blockDim.x + threadIdx.x;
    if (i < NQKV_) g_swa[i] = 0.f;
    if (i < C_)    g_swp[i] = 0.f;
}

// SRC=0: rows of param p -> g_sxa; SRC=1: rows of g_Y -> g_sy. grid = MROWS.
template <int SRC>
__global__ void rowmax_kernel(const float* __restrict__ p) {
    const float* src = (SRC == 1) ? (const float*)g_Y : p;
    float* dst = (SRC == 1) ? g_sy : g_sxa;
    int row = blockIdx.x;
    const float* r = src + (size_t)row * C_;
    float m = 0.f;
    for (int i = threadIdx.x; i < C_; i += 256) m = fmaxf(m, fabsf(r[i]));
#pragma unroll
    for (int o = 16; o > 0; o >>= 1)
        m = fmaxf(m, __shfl_xor_sync(0xffffffffu, m, o));
    __shared__ float wm[8];
    if ((threadIdx.x & 31) == 0) wm[threadIdx.x >> 5] = m;
    __syncthreads();
    if (threadIdx.x == 0) {
        float bm = wm[0];
#pragma unroll
        for (int i = 1; i < 8; i++) bm = fmaxf(bm, wm[i]);
        dst[row] = fmaxf(bm, 1e-30f);
    }
}

// per-column absmax of W[K][N]; grid (N/256, 8), atomicMax merge
template <int WSEL>
__global__ void colmax_kernel(const float* __restrict__ W) {
    float* dst = (WSEL == 1) ? g_swa : g_swp;
    const int N = (WSEL == 1) ? NQKV_ : C_;
    int n = blockIdx.x * 256 + threadIdx.x;
    int k0 = blockIdx.y * 256;
    float m = 0.f;
    for (int k = k0; k < k0 + 256; k++)
        m = fmaxf(m, fabsf(W[(size_t)k * N + n]));
    atomicMax((unsigned*)&dst[n], __float_as_uint(m));
}

// activation -> digit pair with per-row scale; SRC=0 x, SRC=1 g_Y.
template <int SRC>
__global__ void quant_act_kernel(const float* __restrict__ X, int n4) {
    int i = blockIdx.x * blockDim.x + threadIdx.x;
    if (i >= n4) return;
    const float* src = (SRC == 1) ? (const float*)g_Y : X;
    char* __restrict__ D1 = (SRC == 1) ? g_Yd1 : g_xd1;
    char* __restrict__ D2 = (SRC == 1) ? g_Yd2 : g_xd2;
    const float* sr = (SRC == 1) ? g_sy : g_sxa;
    int row = i >> 9;                 // (i*4)/2048
    float inv_s = QMAX / fmaxf(sr[row], 1e-30f);
    float4 v = ((const float4*)src)[i];
    int d1[4], d2[4];
    quant15(v.x, inv_s, d1[0], d2[0]);
    quant15(v.y, inv_s, d1[1], d2[1]);
    quant15(v.z, inv_s, d1[2], d2[2]);
    quant15(v.w, inv_s, d1[3], d2[3]);
    ((char4*)D1)[i] = make_char4((char)d1[0], (char)d1[1], (char)d1[2], (char)d1[3]);
    ((char4*)D2)[i] = make_char4((char)d2[0], (char)d2[1], (char)d2[2], (char)d2[3]);
}

// W[K][N] -> digits [N][K] (transpose + quant, per-column scale)
template <int WSEL>
__global__ void quant_wT_kernel(const float* __restrict__ W) {
    char* __restrict__ Wd1 = (WSEL == 1) ? g_wad1 : g_wpd1;
    char* __restrict__ Wd2 = (WSEL == 1) ? g_wad2 : g_wpd2;
    const float* sc = (WSEL == 1) ? g_swa : g_swp;
    const int K = C_;
    const int N = (WSEL == 1) ? NQKV_ : C_;

    __shared__ float tile[32][33];
    int nb = blockIdx.x * 32, kb = blockIdx.y * 32;
    int tx = threadIdx.x & 31, ty = threadIdx.x >> 5;
#pragma unroll
    for (int r = 0; r < 32; r += 8)
        tile[ty + r][tx] = W[(size_t)(kb + ty + r) * N + nb + tx];
    __syncthreads();
#pragma unroll
    for (int r = 0; r < 32; r += 8) {
        int n = nb + ty + r;
        float inv_s = QMAX / fmaxf(sc[n], 1e-30f);
        float v = tile[tx][ty + r];
        int d1, d2;
        quant15(v, inv_s, d1, d2);
        size_t o = (size_t)n * K + kb + tx;
        Wd1[o] = (char)d1; Wd2[o] = (char)d2;
    }
}

// ---------------------------------------------------------------------------
// RoPE
// ---------------------------------------------------------------------------
__global__ void rope_table_kernel() {
    int i = blockIdx.x * blockDim.x + threadIdx.x;
    if (i >= T_ * 64) return;
    int t = i >> 6, d = i & 63;
    float invf = powf(10000.0f, -(float)d / 64.0f);
    float ang = (float)t * invf;
    g_cos[i] = (float)cos((double)ang);
    g_sin[i] = (float)sin((double)ang);
}

__global__ void rope_apply_kernel() {
    int i = blockIdx.x * blockDim.x + threadIdx.x;
    const int total = B_ * H_ * T_ * 64;
    if (i >= total) return;
    int d  = i & 63;
    int t  = (i >> 6) & (T_ - 1);
    int bh = i >> 17;
    size_t base = ((size_t)bh * T_ + t) * D_;
    float c = g_cos[(t << 6) + d];
    float s = g_sin[(t << 6) + d];
    const float scale = 0.08838834764831845f;  // 1/sqrt(128)
    float q1 = g_Q[base + d], q2 = g_Q[base + d + 64];
    g_Q[base + d]      = (q1 * c - q2 * s) * scale;
    g_Q[base + d + 64] = (q2 * c + q1 * s) * scale;
    float k1 = g_K[base + d], k2 = g_K[base + d + 64];
    g_K[base + d]      = k1 * c - k2 * s;
    g_K[base + d + 64] = k2 * c + k1 * s;
}

// ---------------------------------------------------------------------------
// int8 two-digit GEMM (IMMA m16n8k32), EXACT 15-bit product (4 products):
//   D = s_a[r]*s_b[c]*(65536*hi + 256*cross + lo)
// BK=128 int8, GSTI=144, 2-stage pipeline, 256 threads, warp tile 32x64.
// MODE 1: A=xd, B=wad, epilogue scatters fp32 Q/K/V.
// MODE 2: A=Yd, B=wpd, epilogue fp32 write to Cout.
// ---------------------------------------------------------------------------
#define GBM 128
#define GBN 128
#define IBK 128
#define GSTI 144
#define ITILE (128 * GSTI)
#define ISTAGE (4 * ITILE)
#define GEMM_SMEM_BYTES (2 * ISTAGE) // 147456
#define NKTI 16

__device__ __forceinline__ void store_qkv(int r, int c, float val) {
    int b = r >> 11, t = r & 2047;
    int sec = c >> 11, cc = c & 2047;
    int h = cc >> 7, d = cc & 127;
    size_t dst = (((size_t)(b * H_ + h)) * T_ + t) * D_ + d;
    if (sec == 0)      g_Q[dst] = val;
    else if (sec == 1) g_K[dst] = val;
    else               g_V[dst] = val;
}

template <int MODE>
__global__ void __launch_bounds__(256) gemm_i8_kernel(float* __restrict__ Cout) {
    extern __shared__ __align__(16) char smg[];
    const uint32_t sbase = smem_u32(smg);

    const char* __restrict__ Ad1_g = (MODE == 1) ? g_xd1 : g_Yd1;
    const char* __restrict__ Ad2_g = (MODE == 1) ? g_xd2 : g_Yd2;
    const char* __restrict__ Bd1_g = (MODE == 1) ? g_wad1 : g_wpd1;
    const char* __restrict__ Bd2_g = (MODE == 1) ? g_wad2 : g_wpd2;

    const int tid = threadIdx.x;
    const int lane = tid & 31, warp = tid >> 5;
    const int warpM = warp >> 1, warpN = warp & 1;
    const int gid = lane >> 2, t4 = lane & 3;
    const int bm = blockIdx.y * GBM, bn = blockIdx.x * GBN;

    int acc_hi[2][8][4], acc_cr[2][8][4], acc_lo[2][8][4];
#pragma unroll
    for (int mi = 0; mi < 2; mi++)
#pragma unroll
        for (int ni = 0; ni < 8; ni++)
#pragma unroll
            for (int q = 0; q < 4; q++) {
                acc_hi[mi][ni][q] = 0; acc_cr[mi][ni][q] = 0; acc_lo[mi][ni][q] = 0;
            }

#define ISSUE_STAGE(s, kt) do {                                                   \
    const int kof = (kt) * IBK;                                                   \
    _Pragma("unroll")                                                             \
    for (int i = 0; i < 4; i++) {                                                 \
        int v = tid + i * 256;                                                    \
        int row = v >> 3, kc = (v & 7) * 16;                                      \
        uint32_t dst = sbase + (uint32_t)((s) * ISTAGE + row * GSTI + kc);        \
        size_t srcA = (size_t)(bm + row) * 2048 + kof + kc;                       \
        size_t srcB = (size_t)(bn + row) * 2048 + kof + kc;                       \
        CP_ASYNC16(dst + 0u * ITILE, Ad1_g + srcA);                               \
        CP_ASYNC16(dst + 1u * ITILE, Ad2_g + srcA);                               \
        CP_ASYNC16(dst + 2u * ITILE, Bd1_g + srcB);                               \
        CP_ASYNC16(dst + 3u * ITILE, Bd2_g + srcB);                               \
    }                                                                             \
    CP_COMMIT();                                                                  \
} while (0)

    ISSUE_STAGE(0, 0);
    ISSUE_STAGE(1, 1);

    for (int kt = 0; kt < NKTI; kt++) {
        const int cur = kt & 1;
        if (kt < NKTI - 2) { CP_WAIT1(); } else { CP_WAIT0(); }
        __syncthreads();

        {
            const char* Ad1 = smg + cur * ISTAGE;
            const char* Ad2 = Ad1 + ITILE;
            const char* Bd1 = Ad2 + ITILE;
            const char* Bd2 = Bd1 + ITILE;
#pragma unroll
            for (int ks = 0; ks < IBK; ks += 32) {
                int ko = ks + t4 * 4;
                unsigned a1[2][4], a2[2][4];
#pragma unroll
                for (int mi = 0; mi < 2; mi++) {
                    int r0 = (warpM * 32 + mi * 16 + gid) * GSTI;
                    int r8 = r0 + 8 * GSTI;
                    a1[mi][0] = *(const unsigned*)&Ad1[r0 + ko];
                    a1[mi][1] = *(const unsigned*)&Ad1[r8 + ko];
                    a1[mi][2] = *(const unsigned*)&Ad1[r0 + ko + 16];
                    a1[mi][3] = *(const unsigned*)&Ad1[r8 + ko + 16];
                    a2[mi][0] = *(const unsigned*)&Ad2[r0 + ko];
                    a2[mi][1] = *(const unsigned*)&Ad2[r8 + ko];
                    a2[mi][2] = *(const unsigned*)&Ad2[r0 + ko + 16];
                    a2[mi][3] = *(const unsigned*)&Ad2[r8 + ko + 16];
                }
#pragma unroll
                for (int ni = 0; ni < 8; ni++) {
                    int nb0 = (warpN * 64 + ni * 8 + gid) * GSTI;
                    unsigned b1[2], b2[2];
                    b1[0] = *(const unsigned*)&Bd1[nb0 + ko];
                    b1[1] = *(const unsigned*)&Bd1[nb0 + ko + 16];
                    b2[0] = *(const unsigned*)&Bd2[nb0 + ko];
                    b2[1] = *(const unsigned*)&Bd2[nb0 + ko + 16];
#pragma unroll
                    for (int mi = 0; mi < 2; mi++) {
                        imma_s8(acc_hi[mi][ni], a1[mi], b1);
                        imma_s8(acc_cr[mi][ni], a1[mi], b2);
                        imma_s8(acc_cr[mi][ni], a2[mi], b1);
                        imma_s8(acc_lo[mi][ni], a2[mi], b2);
                    }
                }
            }
        }
        __syncthreads();
        if (kt + 2 < NKTI) ISSUE_STAGE(cur, kt + 2);
    }
#undef ISSUE_STAGE

    // epilogue: per-row / per-column scales
    const float* sa = (MODE == 1) ? g_sxa : g_sy;
    const float* sb = (MODE == 1) ? g_swa : g_swp;
    const float qinv2 = 1.0f / (QMAX * QMAX);
#pragma unroll
    for (int mi = 0; mi < 2; mi++) {
#pragma unroll
        for (int ni = 0; ni < 8; ni++) {
            int r0 = bm + warpM * 32 + mi * 16 + gid;
            int c0 = bn + warpN * 64 + ni * 8 + t4 * 2;
            float sr0 = sa[r0] * qinv2, sr8 = sa[r0 + 8] * qinv2;
            float sc0 = sb[c0], sc1 = sb[c0 + 1];
            float v0 = sr0 * sc0 * (65536.0f * (float)acc_hi[mi][ni][0]
                     + 256.0f * (float)acc_cr[mi][ni][0] + (float)acc_lo[mi][ni][0]);
            float v1 = sr0 * sc1 * (65536.0f * (float)acc_hi[mi][ni][1]
                     + 256.0f * (float)acc_cr[mi][ni][1] + (float)acc_lo[mi][ni][1]);
            float v2 = sr8 * sc0 * (65536.0f * (float)acc_hi[mi][ni][2]
                     + 256.0f * (float)acc_cr[mi][ni][2] + (float)acc_lo[mi][ni][2]);
            float v3 = sr8 * sc1 * (65536.0f * (float)acc_hi[mi][ni][3]
                     + 256.0f * (float)acc_cr[mi][ni][3] + (float)acc_lo[mi][ni][3]);
            if (MODE == 1) {
                store_qkv(r0,     c0,     v0);
                store_qkv(r0,     c0 + 1, v1);
                store_qkv(r0 + 8, c0,     v2);
                store_qkv(r0 + 8, c0 + 1, v3);
            } else {
                Cout[(size_t)r0 * C_ + c0]           = v0;
                Cout[(size_t)r0 * C_ + c0 + 1]       = v1;
                Cout[(size_t)(r0 + 8) * C_ + c0]     = v2;
                Cout[(size_t)(r0 + 8) * C_ + c0 + 1] = v3;
            }
        }
    }
}

// ---------------------------------------------------------------------------
// Flash attention, causal, bf16x3 (round-2 verbatim, fp32 g_Y epilogue).
// ---------------------------------------------------------------------------
#define AQS 136
#define AVS 72
#define O_QH 0
#define O_QL (O_QH + 128 * AQS)
#define O_KH (O_QL + 128 * AQS)
#define O_KL (O_KH + 64 * AQS)
#define O_VTH (O_KL + 64 * AQS)
#define O_VTL (O_VTH + 128 * AVS)
#define O_PH (O_VTL + 128 * AVS)
#define O_PL (O_PH + 128 * AVS)
#define ATT_SMEM_HALVES (O_PL + 128 * AVS)
#define ATT_SMEM_BYTES (ATT_SMEM_HALVES * 2)

__global__ void __launch_bounds__(256) attn_kernel() {
    extern __shared__ __align__(16) __nv_bfloat16 sa_[];
    __nv_bfloat16* Qh  = sa_ + O_QH;
    __nv_bfloat16* Ql  = sa_ + O_QL;
    __nv_bfloat16* Kh  = sa_ + O_KH;
    __nv_bfloat16* Kl  = sa_ + O_KL;
    __nv_bfloat16* VTh = sa_ + O_VTH;
    __nv_bfloat16* VTl = sa_ + O_VTL;
    __nv_bfloat16* Ph  = sa_ + O_PH;
    __nv_bfloat16* Pl  = sa_ + O_PL;

    const int tid = threadIdx.x;
    const int lane = tid & 31, w = tid >> 5;
    const int gid = lane >> 2, t4 = lane & 3;
    const int qtile = blockIdx.x, bh = blockIdx.y;
    const int qbase = qtile * 128;

    const float* Qg = g_Q + ((size_t)bh * T_ + qbase) * D_;
    const float* Kg = g_K + (size_t)bh * T_ * D_;
    const float* Vg = g_V + (size_t)bh * T_ * D_;

#pragma unroll
    for (int i = 0; i < 16; i++) {
        int u = tid + i * 256;
        int row = u >> 5, c4 = (u & 31) << 2;
        float4 v = *(const float4*)(Qg + (size_t)row * D_ + c4);
        unsigned h01, l01, h23, l23;
        split_pair(v.x, v.y, h01, l01);
        split_pair(v.z, v.w, h23, l23);
        *(unsigned*)&Qh[row * AQS + c4]     = h01;
        *(unsigned*)&Qh[row * AQS + c4 + 2] = h23;
        *(unsigned*)&Ql[row * AQS + c4]     = l01;
        *(unsigned*)&Ql[row * AQS + c4 + 2] = l23;
    }

    float o[16][4];
#pragma unroll
    for (int a = 0; a < 16; a++)
#pragma unroll
        for (int c = 0; c < 4; c++) o[a][c] = 0.f;
    float m0 = -1e30f, m1 = -1e30f, l0 = 0.f, l1 = 0.f;

    const int mrow = w * 16;
    const int rl0 = mrow + gid, rl1 = mrow + gid + 8;
    const int njt = 2 * qtile + 2;

    for (int j = 0; j < njt; j++) {
        __syncthreads();
#pragma unroll
        for (int i = 0; i < 8; i++) {
            int u = tid + i * 256;
            int row = u >> 5, c4 = (u & 31) << 2;
            float4 kv = *(const float4*)(Kg + ((size_t)j * 64 + row) * D_ + c4);
            unsigned h01, l01, h23, l23;
            split_pair(kv.x, kv.y, h01, l01);
            split_pair(kv.z, kv.w, h23, l23);
            *(unsigned*)&Kh[row * AQS + c4]     = h01;
            *(unsigned*)&Kh[row * AQS + c4 + 2] = h23;
            *(unsigned*)&Kl[row * AQS + c4]     = l01;
            *(unsigned*)&Kl[row * AQS + c4 + 2] = l23;
        }
#pragma unroll
        for (int i = 0; i < 8; i++) {
            int u = tid + i * 256;
            int d = u & 127, k0 = (u >> 7) << 2;
            float v0 = Vg[((size_t)j * 64 + k0)     * D_ + d];
            float v1 = Vg[((size_t)j * 64 + k0 + 1) * D_ + d];
            float v2 = Vg[((size_t)j * 64 + k0 + 2) * D_ + d];
            float v3 = Vg[((size_t)j * 64 + k0 + 3) * D_ + d];
            unsigned h01, l01, h23, l23;
            split_pair(v0, v1, h01, l01);
            split_pair(v2, v3, h23, l23);
            *(unsigned*)&VTh[d * AVS + k0]     = h01;
            *(unsigned*)&VTh[d * AVS + k0 + 2] = h23;
            *(unsigned*)&VTl[d * AVS + k0]     = l01;
            *(unsigned*)&VTl[d * AVS + k0 + 2] = l23;
        }
        __syncthreads();

        float s[8][4];
#pragma unroll
        for (int ni = 0; ni < 8; ni++)
#pragma unroll
            for (int q = 0; q < 4; q++) s[ni][q] = 0.f;

#pragma unroll
        for (int ks = 0; ks < 128; ks += 16) {
            int ko = ks + 2 * t4;
            unsigned ah[4], al[4];
            ah[0] = *(const unsigned*)&Qh[rl0 * AQS + ko];
            ah[1] = *(const unsigned*)&Qh[rl1 * AQS + ko];
            ah[2] = *(const unsigned*)&Qh[rl0 * AQS + ko + 8];
            ah[3] = *(const unsigned*)&Qh[rl1 * AQS + ko + 8];
            al[0] = *(const unsigned*)&Ql[rl0 * AQS + ko];
            al[1] = *(const unsigned*)&Ql[rl1 * AQS + ko];
            al[2] = *(const unsigned*)&Ql[rl0 * AQS + ko + 8];
            al[3] = *(const unsigned*)&Ql[rl1 * AQS + ko + 8];
#pragma unroll
            for (int ni = 0; ni < 8; ni++) {
                int nc = ni * 8 + gid;
                unsigned bhf[2], blf[2];
                bhf[0] = *(const unsigned*)&Kh[nc * AQS + ko];
                bhf[1] = *(const unsigned*)&Kh[nc * AQS + ko + 8];
                blf[0] = *(const unsigned*)&Kl[nc * AQS + ko];
                blf[1] = *(const unsigned*)&Kl[nc * AQS + ko + 8];
                mma_3x(s[ni], ah, al, bhf, blf);
            }
        }

        if (j >= 2 * qtile) {
            const int rg0 = qbase + rl0, rg1 = qbase + rl1;
#pragma unroll
            for (int ni = 0; ni < 8; ni++) {
                int cg = j * 64 + ni * 8 + t4 * 2;
                if (cg     > rg0) s[ni][0] = -1e30f;
                if (cg + 1 > rg0) s[ni][1] = -1e30f;
                if (cg     > rg1) s[ni][2] = -1e30f;
                if (cg + 1 > rg1) s[ni][3] = -1e30f;
            }
        }

        float rmax0 = -1e30f, rmax1 = -1e30f;
#pragma unroll
        for (int ni = 0; ni < 8; ni++) {
            rmax0 = fmaxf(rmax0, fmaxf(s[ni][0], s[ni][1]));
            rmax1 = fmaxf(rmax1, fmaxf(s[ni][2], s[ni][3]));
        }
        rmax0 = fmaxf(rmax0, __shfl_xor_sync(0xffffffffu, rmax0, 1));
        rmax0 = fmaxf(rmax0, __shfl_xor_sync(0xffffffffu, rmax0, 2));
        rmax1 = fmaxf(rmax1, __shfl_xor_sync(0xffffffffu, rmax1, 1));
        rmax1 = fmaxf(rmax1, __shfl_xor_sync(0xffffffffu, rmax1, 2));

        float nm0 = fmaxf(m0, rmax0), nm1 = fmaxf(m1, rmax1);
        float a0 = __expf(m0 - nm0), a1 = __expf(m1 - nm1);
        m0 = nm0; m1 = nm1;

        float sum0 = 0.f, sum1 = 0.f;
#pragma unroll
        for (int ni = 0; ni < 8; ni++) {
            s[ni][0] = __expf(s[ni][0] - nm0);
            s[ni][1] = __expf(s[ni][1] - nm0);
            s[ni][2] = __expf(s[ni][2] - nm1);
            s[ni][3] = __expf(s[ni][3] - nm1);
            sum0 += s[ni][0] + s[ni][1];
            sum1 += s[ni][2] + s[ni][3];
        }
        sum0 += __shfl_xor_sync(0xffffffffu, sum0, 1);
        sum0 += __shfl_xor_sync(0xffffffffu, sum0, 2);
        sum1 += __shfl_xor_sync(0xffffffffu, sum1, 1);
        sum1 += __shfl_xor_sync(0xffffffffu, sum1, 2);
        l0 = l0 * a0 + sum0;
        l1 = l1 * a1 + sum1;

#pragma unroll
        for (int di = 0; di < 16; di++) {
            o[di][0] *= a0; o[di][1] *= a0;
            o[di][2] *= a1; o[di][3] *= a1;
        }

#pragma unroll
        for (int ni = 0; ni < 8; ni++) {
            int cc = ni * 8 + 2 * t4;
            unsigned h01, lo01, h23, lo23;
            split_pair(s[ni][0], s[ni][1], h01, lo01);
            split_pair(s[ni][2], s[ni][3], h23, lo23);
            *(unsigned*)&Ph[rl0 * AVS + cc] = h01;
            *(unsigned*)&Pl[rl0 * AVS + cc] = lo01;
            *(unsigned*)&Ph[rl1 * AVS + cc] = h23;
            *(unsigned*)&Pl[rl1 * AVS + cc] = lo23;
        }
        __syncwarp();

#pragma unroll
        for (int kk = 0; kk < 64; kk += 16) {
            int ko = kk + 2 * t4;
            unsigned ah[4], al[4];
            ah[0] = *(const unsigned*)&Ph[rl0 * AVS + ko];
            ah[1] = *(const unsigned*)&Ph[rl1 * AVS + ko];
            ah[2] = *(const unsigned*)&Ph[rl0 * AVS + ko + 8];
            ah[3] = *(const unsigned*)&Ph[rl1 * AVS + ko + 8];
            al[0] = *(const unsigned*)&Pl[rl0 * AVS + ko];
            al[1] = *(const unsigned*)&Pl[rl1 * AVS + ko];
            al[2] = *(const unsigned*)&Pl[rl0 * AVS + ko + 8];
            al[3] = *(const unsigned*)&Pl[rl1 * AVS + ko + 8];
#pragma unroll
            for (int di = 0; di < 16; di++) {
                int nc = di * 8 + gid;
                unsigned bhf[2], blf[2];
                bhf[0] = *(const unsigned*)&VTh[nc * AVS + ko];
                bhf[1] = *(const unsigned*)&VTh[nc * AVS + ko + 8];
                blf[0] = *(const unsigned*)&VTl[nc * AVS + ko];
                blf[1] = *(const unsigned*)&VTl[nc * AVS + ko + 8];
                mma_3x(o[di], ah, al, bhf, blf);
            }
        }
    }

    // Normalize + write fp32 g_Y (quantized in a later pass w/ per-row scale)
    float il0 = 1.0f / l0, il1 = 1.0f / l1;
    int b = bh >> 4, h = bh & 15;
    int rg0 = qbase + rl0, rg1 = qbase + rl1;
#pragma unroll
    for (int di = 0; di < 16; di++) {
        size_t base0 = ((size_t)b * T_ + rg0) * C_ + h * D_ + di * 8 + t4 * 2;
        size_t base1 = ((size_t)b * T_ + rg1) * C_ + h * D_ + di * 8 + t4 * 2;
        g_Y[base0]     = o[di][0] * il0;
        g_Y[base0 + 1] = o[di][1] * il0;
        g_Y[base1]     = o[di][2] * il1;
        g_Y[base1 + 1] = o[di][3] * il1;
    }
}

// ---------------------------------------------------------------------------
// Launch
// ---------------------------------------------------------------------------
extern "C" void kernel_launch(void* const* d_in, const int* in_sizes, int n_in,
                              void* d_out, int out_size) {
    const float* x      = (const float*)d_in[0];
    const float* w_attn = (const float*)d_in[1];
    const float* w_proj = (const float*)d_in[2];
    float* out = (float*)d_out;
    (void)in_sizes; (void)n_in; (void)out_size;

    cudaFuncSetAttribute(attn_kernel, cudaFuncAttributeMaxDynamicSharedMemorySize,
                         ATT_SMEM_BYTES);
    cudaFuncSetAttribute(gemm_i8_kernel<1>,
                         cudaFuncAttributeMaxDynamicSharedMemorySize, GEMM_SMEM_BYTES);
    cudaFuncSetAttribute(gemm_i8_kernel<2>,
                         cudaFuncAttributeMaxDynamicSharedMemorySize, GEMM_SMEM_BYTES);

    // per-row / per-column scales + quantization of inputs
    rope_table_kernel<<<(T_ * 64 + 255) / 256, 256>>>();
    zero_colmax_kernel<<<(NQKV_ + 255) / 256, 256>>>();
    rowmax_kernel<0><<<MROWS, 256>>>(x);
    colmax_kernel<1><<<dim3(NQKV_ / 256, 8), 256>>>(w_attn);
    colmax_kernel<2><<<dim3(C_ / 256, 8), 256>>>(w_proj);
    quant_act_kernel<0><<<(MROWS * C_ / 4 + 255) / 256, 256>>>(x, MROWS * C_ / 4);
    quant_wT_kernel<1><<<dim3(NQKV_ / 32, C_ / 32), 256>>>(w_attn);
    quant_wT_kernel<2><<<dim3(C_ / 32, C_ / 32), 256>>>(w_proj);

    // QKV GEMM (int8 IMMA, exact 15-bit) -> fp32 g_Q/K/V
    gemm_i8_kernel<1><<<dim3(NQKV_ / GBN, MROWS / GBM), 256, GEMM_SMEM_BYTES>>>(nullptr);

    // RoPE + scale fold
    rope_apply_kernel<<<(B_ * H_ * T_ * 64 + 255) / 256, 256>>>();

    // attention (bf16x3) -> fp32 g_Y
    attn_kernel<<<dim3(T_ / 128, B_ * H_), 256, ATT_SMEM_BYTES>>>();

    // per-row Y scale + quantize Y
    rowmax_kernel<1><<<MROWS, 256>>>(nullptr);
    quant_act_kernel<1><<<(MROWS * C_ / 4 + 255) / 256, 256>>>(nullptr, MROWS * C_ / 4);

    // out projection (int8 IMMA, exact 15-bit) -> d_out
    gemm_i8_kernel<2><<<dim3(C_ / GBN, MROWS / GBM), 256, GEMM_SMEM_BYTES>>>(out);
}

// round 15
// speedup vs baseline: 2.5737x; 2.5737x over previous
#include <cuda_runtime.h>
#include <cuda_bf16.h>
#include <math.h>

// Problem constants
#define B_    4
#define T_    2048
#define C_    2048
#define H_    16
#define D_    128
#define NQKV_ 6144   // 3*C_
#define MROWS 8192   // B_*T_

// ---------------------------------------------------------------------------
// Scratch (device globals — no allocations allowed)
// ---------------------------------------------------------------------------
__device__ __align__(256) float g_Q[(size_t)B_ * H_ * T_ * D_];
__device__ __align__(256) float g_K[(size_t)B_ * H_ * T_ * D_];
__device__ __align__(256) float g_V[(size_t)B_ * H_ * T_ * D_];
__device__ __align__(256) float g_Y[(size_t)B_ * T_ * C_];
__device__ __align__(256) float g_cos[T_ * 64];
__device__ __align__(256) float g_sin[T_ * 64];

// ---------------------------------------------------------------------------
// bf16x3 helpers: x = hi + lo (two bf16), D += ah*bl + al*bh + ah*bh
// ---------------------------------------------------------------------------
__device__ __forceinline__ void split_pair(float x0, float x1, unsigned& h, unsigned& l) {
    __nv_bfloat16 h0 = __float2bfloat16_rn(x0);
    __nv_bfloat16 h1 = __float2bfloat16_rn(x1);
    __nv_bfloat16 l0 = __float2bfloat16_rn(x0 - __bfloat162float(h0));
    __nv_bfloat16 l1 = __float2bfloat16_rn(x1 - __bfloat162float(h1));
    __nv_bfloat162 hh = __halves2bfloat162(h0, h1);
    __nv_bfloat162 ll = __halves2bfloat162(l0, l1);
    h = *reinterpret_cast<unsigned*>(&hh);
    l = *reinterpret_cast<unsigned*>(&ll);
}

__device__ __forceinline__ void mma_bf16(float c[4], const unsigned a[4], const unsigned b[2]) {
    asm volatile(
        "mma.sync.aligned.m16n8k16.row.col.f32.bf16.bf16.f32 "
        "{%0,%1,%2,%3}, {%4,%5,%6,%7}, {%8,%9}, {%0,%1,%2,%3};"
        : "+f"(c[0]), "+f"(c[1]), "+f"(c[2]), "+f"(c[3])
        : "r"(a[0]), "r"(a[1]), "r"(a[2]), "r"(a[3]), "r"(b[0]), "r"(b[1]));
}

__device__ __forceinline__ void mma_3x(float c[4],
                                       const unsigned ah[4], const unsigned al[4],
                                       const unsigned bh[2], const unsigned bl[2]) {
    mma_bf16(c, ah, bl);
    mma_bf16(c, al, bh);
    mma_bf16(c, ah, bh);
}

// ---------------------------------------------------------------------------
// RoPE tables
// ---------------------------------------------------------------------------
__global__ void rope_table_kernel() {
    int i = blockIdx.x * blockDim.x + threadIdx.x;
    if (i >= T_ * 64) return;
    int t = i >> 6, d = i & 63;
    float invf = powf(10000.0f, -(float)d / 64.0f);
    float ang = (float)t * invf;
    g_cos[i] = (float)cos((double)ang);
    g_sin[i] = (float)sin((double)ang);
}

// ---------------------------------------------------------------------------
// RoPE apply (in place on g_Q / g_K), fold 1/sqrt(D) into Q.
// ---------------------------------------------------------------------------
__global__ void rope_apply_kernel() {
    int i = blockIdx.x * blockDim.x + threadIdx.x;
    const int total = B_ * H_ * T_ * 64;
    if (i >= total) return;
    int d  = i & 63;
    int t  = (i >> 6) & (T_ - 1);
    int bh = i >> 17;
    size_t base = ((size_t)bh * T_ + t) * D_;
    float c = g_cos[(t << 6) + d];
    float s = g_sin[(t << 6) + d];
    const float scale = 0.08838834764831845f;  // 1/sqrt(128)
    float q1 = g_Q[base + d], q2 = g_Q[base + d + 64];
    g_Q[base + d]      = (q1 * c - q2 * s) * scale;
    g_Q[base + d + 64] = (q2 * c + q1 * s) * scale;
    float k1 = g_K[base + d], k2 = g_K[base + d + 64];
    g_K[base + d]      = k1 * c - k2 * s;
    g_K[base + d + 64] = k2 * c + k1 * s;
}

// ---------------------------------------------------------------------------
// bf16x3 GEMM: C[M,N] = A[M,K] @ B[K,N] (row-major fp32 in/out)
// Split to bf16 hi/lo at smem-store time. BM=128, BN=128, BK=32, 256 thr.
// A smem: [128][40] halves (k contiguous). B smem: [128 n][40 k] (transposed).
// MODE 1: epilogue scatters into g_Q/g_K/g_V.  MODE 2: A = g_Y, plain C write.
// ---------------------------------------------------------------------------
#define GBM 128
#define GBN 128
#define GBK 32
#define GST 40
#define GTILE (128 * GST)
#define GEMM_SMEM_BYTES (2 * 4 * GTILE * 2)   // 2 stages * 4 tiles * halves*2B

__device__ __forceinline__ void store_qkv(int r, int c, float val) {
    int b = r >> 11, t = r & 2047;
    int sec = c >> 11, cc = c & 2047;
    int h = cc >> 7, d = cc & 127;
    size_t dst = (((size_t)(b * H_ + h)) * T_ + t) * D_ + d;
    if (sec == 0)      g_Q[dst] = val;
    else if (sec == 1) g_K[dst] = val;
    else               g_V[dst] = val;
}

template <int MODE>
__global__ void __launch_bounds__(256) gemm_bf16x3_kernel(
    const float* __restrict__ A_in, const float* __restrict__ B_in,
    float* __restrict__ C, int M, int N, int K)
{
    extern __shared__ __align__(16) __nv_bfloat16 smg[];
    const float* A = (MODE == 2) ? (const float*)g_Y : A_in;

    const int tid = threadIdx.x;
    const int lane = tid & 31, warp = tid >> 5;
    const int warpM = warp >> 1, warpN = warp & 1;
    const int gid = lane >> 2, t4 = lane & 3;
    const int bm = blockIdx.y * GBM, bn = blockIdx.x * GBN;

    float acc[2][8][4];
#pragma unroll
    for (int mi = 0; mi < 2; mi++)
#pragma unroll
        for (int ni = 0; ni < 8; ni++)
#pragma unroll
            for (int q = 0; q < 4; q++) acc[mi][ni][q] = 0.f;

    // loader geometry (constant per thread)
    const int a_row0 = tid >> 3;          // + i*32
    const int a_c4   = (tid & 7) * 4;
    const int b_n    = tid & 127;         // column of B tile
    const int b_k0b  = (tid >> 7) * 4;    // + i*8

    const int nk = K / GBK;

    float4 pa[4];
    float  pb[16];

    // ---- prefetch tile kt into registers
#define G_PREFETCH(kt) do {                                                        \
    _Pragma("unroll")                                                              \
    for (int i = 0; i < 4; i++)                                                    \
        pa[i] = *(const float4*)(A + (size_t)(bm + a_row0 + i * 32) * K            \
                                   + (kt) * GBK + a_c4);                           \
    _Pragma("unroll")                                                              \
    for (int i = 0; i < 4; i++) {                                                  \
        const float* bp = B_in + (size_t)((kt) * GBK + b_k0b + i * 8) * N + bn + b_n; \
        pb[i*4+0] = bp[0]; pb[i*4+1] = bp[N];                                      \
        pb[i*4+2] = bp[2*(size_t)N]; pb[i*4+3] = bp[3*(size_t)N];                  \
    }                                                                              \
} while (0)

    // ---- split registers into stage s
#define G_STORE(s) do {                                                            \
    __nv_bfloat16* Ah = smg + (s) * 4 * GTILE;                                     \
    __nv_bfloat16* Al = Ah + GTILE;                                                \
    __nv_bfloat16* Bh = Al + GTILE;                                                \
    __nv_bfloat16* Bl = Bh + GTILE;                                                \
    _Pragma("unroll")                                                              \
    for (int i = 0; i < 4; i++) {                                                  \
        int row = a_row0 + i * 32;                                                 \
        unsigned h01, l01, h23, l23;                                               \
        split_pair(pa[i].x, pa[i].y, h01, l01);                                    \
        split_pair(pa[i].z, pa[i].w, h23, l23);                                    \
        *(unsigned*)&Ah[row * GST + a_c4]     = h01;                               \
        *(unsigned*)&Ah[row * GST + a_c4 + 2] = h23;                               \
        *(unsigned*)&Al[row * GST + a_c4]     = l01;                               \
        *(unsigned*)&Al[row * GST + a_c4 + 2] = l23;                               \
    }                                                                              \
    _Pragma("unroll")                                                              \
    for (int i = 0; i < 4; i++) {                                                  \
        int k0 = b_k0b + i * 8;                                                    \
        unsigned h01, l01, h23, l23;                                               \
        split_pair(pb[i*4+0], pb[i*4+1], h01, l01);                                \
        split_pair(pb[i*4+2], pb[i*4+3], h23, l23);                                \
        *(unsigned*)&Bh[b_n * GST + k0]     = h01;                                 \
        *(unsigned*)&Bh[b_n * GST + k0 + 2] = h23;                                 \
        *(unsigned*)&Bl[b_n * GST + k0]     = l01;                                 \
        *(unsigned*)&Bl[b_n * GST + k0 + 2] = l23;                                 \
    }                                                                              \
} while (0)

    G_PREFETCH(0);
    G_STORE(0);
    __syncthreads();

    for (int kt = 0; kt < nk; kt++) {
        const int cur = kt & 1;
        if (kt + 1 < nk) G_PREFETCH(kt + 1);

        {
            const __nv_bfloat16* Ah = smg + cur * 4 * GTILE;
            const __nv_bfloat16* Al = Ah + GTILE;
            const __nv_bfloat16* Bh = Al + GTILE;
            const __nv_bfloat16* Bl = Bh + GTILE;
#pragma unroll
            for (int ks = 0; ks < GBK; ks += 16) {
                unsigned ah[2][4], al[2][4];
#pragma unroll
                for (int mi = 0; mi < 2; mi++) {
                    int r0 = warpM * 32 + mi * 16 + gid;
                    int ko = ks + 2 * t4;
                    ah[mi][0] = *(const unsigned*)&Ah[r0 * GST + ko];
                    ah[mi][1] = *(const unsigned*)&Ah[(r0 + 8) * GST + ko];
                    ah[mi][2] = *(const unsigned*)&Ah[r0 * GST + ko + 8];
                    ah[mi][3] = *(const unsigned*)&Ah[(r0 + 8) * GST + ko + 8];
                    al[mi][0] = *(const unsigned*)&Al[r0 * GST + ko];
                    al[mi][1] = *(const unsigned*)&Al[(r0 + 8) * GST + ko];
                    al[mi][2] = *(const unsigned*)&Al[r0 * GST + ko + 8];
                    al[mi][3] = *(const unsigned*)&Al[(r0 + 8) * GST + ko + 8];
                }
#pragma unroll
                for (int ni = 0; ni < 8; ni++) {
                    int nc = warpN * 64 + ni * 8 + gid;
                    int ko = ks + 2 * t4;
                    unsigned bh[2], bl[2];
                    bh[0] = *(const unsigned*)&Bh[nc * GST + ko];
                    bh[1] = *(const unsigned*)&Bh[nc * GST + ko + 8];
                    bl[0] = *(const unsigned*)&Bl[nc * GST + ko];
                    bl[1] = *(const unsigned*)&Bl[nc * GST + ko + 8];
#pragma unroll
                    for (int mi = 0; mi < 2; mi++)
                        mma_3x(acc[mi][ni], ah[mi], al[mi], bh, bl);
                }
            }
        }

        if (kt + 1 < nk) G_STORE(cur ^ 1);
        __syncthreads();
    }
#undef G_PREFETCH
#undef G_STORE

    // epilogue
#pragma unroll
    for (int mi = 0; mi < 2; mi++) {
#pragma unroll
        for (int ni = 0; ni < 8; ni++) {
            int r0 = bm + warpM * 32 + mi * 16 + gid;
            int c0 = bn + warpN * 64 + ni * 8 + t4 * 2;
            if (MODE == 1) {
                store_qkv(r0,     c0,     acc[mi][ni][0]);
                store_qkv(r0,     c0 + 1, acc[mi][ni][1]);
                store_qkv(r0 + 8, c0,     acc[mi][ni][2]);
                store_qkv(r0 + 8, c0 + 1, acc[mi][ni][3]);
            } else {
                C[(size_t)r0 * N + c0]           = acc[mi][ni][0];
                C[(size_t)r0 * N + c0 + 1]       = acc[mi][ni][1];
                C[(size_t)(r0 + 8) * N + c0]     = acc[mi][ni][2];
                C[(size_t)(r0 + 8) * N + c0 + 1] = acc[mi][ni][3];
            }
        }
    }
}

// ---------------------------------------------------------------------------
// Flash attention, causal, bf16x3. Br=128 (8 warps x 16 rows), Bc=64, D=128.
// ---------------------------------------------------------------------------
#define AQS 136   // Q/K k-stride (halves)
#define AVS 72    // VT/P k-stride (halves)

#define O_QH 0
#define O_QL (O_QH + 128 * AQS)
#define O_KH (O_QL + 128 * AQS)
#define O_KL (O_KH + 64 * AQS)
#define O_VTH (O_KL + 64 * AQS)
#define O_VTL (O_VTH + 128 * AVS)
#define O_PH (O_VTL + 128 * AVS)
#define O_PL (O_PH + 128 * AVS)
#define ATT_SMEM_HALVES (O_PL + 128 * AVS)
#define ATT_SMEM_BYTES (ATT_SMEM_HALVES * 2)

__global__ void __launch_bounds__(256) attn_kernel() {
    extern __shared__ __align__(16) __nv_bfloat16 sa[];
    __nv_bfloat16* Qh  = sa + O_QH;
    __nv_bfloat16* Ql  = sa + O_QL;
    __nv_bfloat16* Kh  = sa + O_KH;
    __nv_bfloat16* Kl  = sa + O_KL;
    __nv_bfloat16* VTh = sa + O_VTH;
    __nv_bfloat16* VTl = sa + O_VTL;
    __nv_bfloat16* Ph  = sa + O_PH;
    __nv_bfloat16* Pl  = sa + O_PL;

    const int tid = threadIdx.x;
    const int lane = tid & 31, w = tid >> 5;
    const int gid = lane >> 2, t4 = lane & 3;
    const int qtile = blockIdx.x, bh = blockIdx.y;
    const int qbase = qtile * 128;

    const float* Qg = g_Q + ((size_t)bh * T_ + qbase) * D_;
    const float* Kg = g_K + (size_t)bh * T_ * D_;
    const float* Vg = g_V + (size_t)bh * T_ * D_;

    // Load + split Q tile (128 x 128)
#pragma unroll
    for (int i = 0; i < 16; i++) {
        int u = tid + i * 256;
        int row = u >> 5, c4 = (u & 31) << 2;
        float4 v = *(const float4*)(Qg + (size_t)row * D_ + c4);
        unsigned h01, l01, h23, l23;
        split_pair(v.x, v.y, h01, l01);
        split_pair(v.z, v.w, h23, l23);
        *(unsigned*)&Qh[row * AQS + c4]     = h01;
        *(unsigned*)&Qh[row * AQS + c4 + 2] = h23;
        *(unsigned*)&Ql[row * AQS + c4]     = l01;
        *(unsigned*)&Ql[row * AQS + c4 + 2] = l23;
    }

    float o[16][4];
#pragma unroll
    for (int a = 0; a < 16; a++)
#pragma unroll
        for (int c = 0; c < 4; c++) o[a][c] = 0.f;
    float m0 = -1e30f, m1 = -1e30f, l0 = 0.f, l1 = 0.f;

    const int mrow = w * 16;
    const int rl0 = mrow + gid, rl1 = mrow + gid + 8;
    const int njt = 2 * qtile + 2;

    for (int j = 0; j < njt; j++) {
        __syncthreads();
        // K tile: [64 rows][128 k]
#pragma unroll
        for (int i = 0; i < 8; i++) {
            int u = tid + i * 256;
            int row = u >> 5, c4 = (u & 31) << 2;
            float4 kv = *(const float4*)(Kg + ((size_t)j * 64 + row) * D_ + c4);
            unsigned h01, l01, h23, l23;
            split_pair(kv.x, kv.y, h01, l01);
            split_pair(kv.z, kv.w, h23, l23);
            *(unsigned*)&Kh[row * AQS + c4]     = h01;
            *(unsigned*)&Kh[row * AQS + c4 + 2] = h23;
            *(unsigned*)&Kl[row * AQS + c4]     = l01;
            *(unsigned*)&Kl[row * AQS + c4 + 2] = l23;
        }
        // V tile transposed: VT[d][k], k packed in pairs
#pragma unroll
        for (int i = 0; i < 8; i++) {
            int u = tid + i * 256;
            int d = u & 127, k0 = (u >> 7) << 2;
            float v0 = Vg[((size_t)j * 64 + k0)     * D_ + d];
            float v1 = Vg[((size_t)j * 64 + k0 + 1) * D_ + d];
            float v2 = Vg[((size_t)j * 64 + k0 + 2) * D_ + d];
            float v3 = Vg[((size_t)j * 64 + k0 + 3) * D_ + d];
            unsigned h01, l01, h23, l23;
            split_pair(v0, v1, h01, l01);
            split_pair(v2, v3, h23, l23);
            *(unsigned*)&VTh[d * AVS + k0]     = h01;
            *(unsigned*)&VTh[d * AVS + k0 + 2] = h23;
            *(unsigned*)&VTl[d * AVS + k0]     = l01;
            *(unsigned*)&VTl[d * AVS + k0 + 2] = l23;
        }
        __syncthreads();

        // S = Q K^T (128x64), bf16x3
        float s[8][4];
#pragma unroll
        for (int ni = 0; ni < 8; ni++)
#pragma unroll
            for (int q = 0; q < 4; q++) s[ni][q] = 0.f;

#pragma unroll
        for (int ks = 0; ks < 128; ks += 16) {
            int ko = ks + 2 * t4;
            unsigned ah[4], al[4];
            ah[0] = *(const unsigned*)&Qh[rl0 * AQS + ko];
            ah[1] = *(const unsigned*)&Qh[rl1 * AQS + ko];
            ah[2] = *(const unsigned*)&Qh[rl0 * AQS + ko + 8];
            ah[3] = *(const unsigned*)&Qh[rl1 * AQS + ko + 8];
            al[0] = *(const unsigned*)&Ql[rl0 * AQS + ko];
            al[1] = *(const unsigned*)&Ql[rl1 * AQS + ko];
            al[2] = *(const unsigned*)&Ql[rl0 * AQS + ko + 8];
            al[3] = *(const unsigned*)&Ql[rl1 * AQS + ko + 8];
#pragma unroll
            for (int ni = 0; ni < 8; ni++) {
                int nc = ni * 8 + gid;
                unsigned bhf[2], blf[2];
                bhf[0] = *(const unsigned*)&Kh[nc * AQS + ko];
                bhf[1] = *(const unsigned*)&Kh[nc * AQS + ko + 8];
                blf[0] = *(const unsigned*)&Kl[nc * AQS + ko];
                blf[1] = *(const unsigned*)&Kl[nc * AQS + ko + 8];
                mma_3x(s[ni], ah, al, bhf, blf);
            }
        }

        // Causal mask
        if (j >= 2 * qtile) {
            const int rg0 = qbase + rl0, rg1 = qbase + rl1;
#pragma unroll
            for (int ni = 0; ni < 8; ni++) {
                int cg = j * 64 + ni * 8 + t4 * 2;
                if (cg     > rg0) s[ni][0] = -1e30f;
                if (cg + 1 > rg0) s[ni][1] = -1e30f;
                if (cg     > rg1) s[ni][2] = -1e30f;
                if (cg + 1 > rg1) s[ni][3] = -1e30f;
            }
        }

        // Online softmax
        float rmax0 = -1e30f, rmax1 = -1e30f;
#pragma unroll
        for (int ni = 0; ni < 8; ni++) {
            rmax0 = fmaxf(rmax0, fmaxf(s[ni][0], s[ni][1]));
            rmax1 = fmaxf(rmax1, fmaxf(s[ni][2], s[ni][3]));
        }
        rmax0 = fmaxf(rmax0, __shfl_xor_sync(0xffffffffu, rmax0, 1));
        rmax0 = fmaxf(rmax0, __shfl_xor_sync(0xffffffffu, rmax0, 2));
        rmax1 = fmaxf(rmax1, __shfl_xor_sync(0xffffffffu, rmax1, 1));
        rmax1 = fmaxf(rmax1, __shfl_xor_sync(0xffffffffu, rmax1, 2));

        float nm0 = fmaxf(m0, rmax0), nm1 = fmaxf(m1, rmax1);
        float a0 = __expf(m0 - nm0), a1 = __expf(m1 - nm1);
        m0 = nm0; m1 = nm1;

        float sum0 = 0.f, sum1 = 0.f;
#pragma unroll
        for (int ni = 0; ni < 8; ni++) {
            s[ni][0] = __expf(s[ni][0] - nm0);
            s[ni][1] = __expf(s[ni][1] - nm0);
            s[ni][2] = __expf(s[ni][2] - nm1);
            s[ni][3] = __expf(s[ni][3] - nm1);
            sum0 += s[ni][0] + s[ni][1];
            sum1 += s[ni][2] + s[ni][3];
        }
        sum0 += __shfl_xor_sync(0xffffffffu, sum0, 1);
        sum0 += __shfl_xor_sync(0xffffffffu, sum0, 2);
        sum1 += __shfl_xor_sync(0xffffffffu, sum1, 1);
        sum1 += __shfl_xor_sync(0xffffffffu, sum1, 2);
        l0 = l0 * a0 + sum0;
        l1 = l1 * a1 + sum1;

#pragma unroll
        for (int di = 0; di < 16; di++) {
            o[di][0] *= a0; o[di][1] *= a0;
            o[di][2] *= a1; o[di][3] *= a1;
        }

        // P -> smem (split bf16 hi/lo, per-warp region)
#pragma unroll
        for (int ni = 0; ni < 8; ni++) {
            int cc = ni * 8 + 2 * t4;
            unsigned h01, lo01, h23, lo23;
            split_pair(s[ni][0], s[ni][1], h01, lo01);
            split_pair(s[ni][2], s[ni][3], h23, lo23);
            *(unsigned*)&Ph[rl0 * AVS + cc] = h01;
            *(unsigned*)&Pl[rl0 * AVS + cc] = lo01;
            *(unsigned*)&Ph[rl1 * AVS + cc] = h23;
            *(unsigned*)&Pl[rl1 * AVS + cc] = lo23;
        }
        __syncwarp();

        // O += P @ V (bf16x3); V supplied transposed as B operand
#pragma unroll
        for (int kk = 0; kk < 64; kk += 16) {
            int ko = kk + 2 * t4;
            unsigned ah[4], al[4];
            ah[0] = *(const unsigned*)&Ph[rl0 * AVS + ko];
            ah[1] = *(const unsigned*)&Ph[rl1 * AVS + ko];
            ah[2] = *(const unsigned*)&Ph[rl0 * AVS + ko + 8];
            ah[3] = *(const unsigned*)&Ph[rl1 * AVS + ko + 8];
            al[0] = *(const unsigned*)&Pl[rl0 * AVS + ko];
            al[1] = *(const unsigned*)&Pl[rl1 * AVS + ko];
            al[2] = *(const unsigned*)&Pl[rl0 * AVS + ko + 8];
            al[3] = *(const unsigned*)&Pl[rl1 * AVS + ko + 8];
#pragma unroll
            for (int di = 0; di < 16; di++) {
                int nc = di * 8 + gid;
                unsigned bhf[2], blf[2];
                bhf[0] = *(const unsigned*)&VTh[nc * AVS + ko];
                bhf[1] = *(const unsigned*)&VTh[nc * AVS + ko + 8];
                blf[0] = *(const unsigned*)&VTl[nc * AVS + ko];
                blf[1] = *(const unsigned*)&VTl[nc * AVS + ko + 8];
                mma_3x(o[di], ah, al, bhf, blf);
            }
        }
    }

    // Normalize + write to g_Y [B,T,C]
    float il0 = 1.0f / l0, il1 = 1.0f / l1;
    int b = bh >> 4, h = bh & 15;
    int rg0 = qbase + rl0, rg1 = qbase + rl1;
#pragma unroll
    for (int di = 0; di < 16; di++) {
        size_t base0 = ((size_t)b * T_ + rg0) * C_ + h * D_ + di * 8 + t4 * 2;
        size_t base1 = ((size_t)b * T_ + rg1) * C_ + h * D_ + di * 8 + t4 * 2;
        g_Y[base0]     = o[di][0] * il0;
        g_Y[base0 + 1] = o[di][1] * il0;
        g_Y[base1]     = o[di][2] * il1;
        g_Y[base1 + 1] = o[di][3] * il1;
    }
}

// ---------------------------------------------------------------------------
// Launch
// ---------------------------------------------------------------------------
extern "C" void kernel_launch(void* const* d_in, const int* in_sizes, int n_in,
                              void* d_out, int out_size) {
    const float* x      = (const float*)d_in[0];
    const float* w_attn = (const float*)d_in[1];
    const float* w_proj = (const float*)d_in[2];
    float* out = (float*)d_out;

    (void)in_sizes; (void)n_in; (void)out_size;

    cudaFuncSetAttribute(attn_kernel, cudaFuncAttributeMaxDynamicSharedMemorySize,
                         ATT_SMEM_BYTES);
    cudaFuncSetAttribute(gemm_bf16x3_kernel<1>,
                         cudaFuncAttributeMaxDynamicSharedMemorySize, GEMM_SMEM_BYTES);
    cudaFuncSetAttribute(gemm_bf16x3_kernel<2>,
                         cudaFuncAttributeMaxDynamicSharedMemorySize, GEMM_SMEM_BYTES);

    // 1. RoPE tables
    rope_table_kernel<<<(T_ * 64 + 255) / 256, 256>>>();

    // 2. QKV GEMM (x @ w_attn) -> g_Q/g_K/g_V in [B,H,T,D]
    gemm_bf16x3_kernel<1><<<dim3(NQKV_ / GBN, MROWS / GBM), 256, GEMM_SMEM_BYTES>>>(
        x, w_attn, nullptr, MROWS, NQKV_, C_);

    // 3. RoPE + scale fold
    rope_apply_kernel<<<(B_ * H_ * T_ * 64 + 255) / 256, 256>>>();

    // 4. Causal flash attention -> g_Y [B,T,C]
    attn_kernel<<<dim3(T_ / 128, B_ * H_), 256, ATT_SMEM_BYTES>>>();

    // 5. Output projection (g_Y @ w_proj) -> d_out
    gemm_bf16x3_kernel<2><<<dim3(C_ / GBN, MROWS / GBM), 256, GEMM_SMEM_BYTES>>>(
        nullptr, w_proj, out, MROWS, C_, C_);
}

// round 16
// speedup vs baseline: 2.6767x; 1.0400x over previous
#include <cuda_runtime.h>
#include <cuda_bf16.h>
#include <math.h>
#include <stdint.h>

// Problem constants
#define B_    4
#define T_    2048
#define C_    2048
#define H_    16
#define D_    128
#define NQKV_ 6144
#define MROWS 8192

// ---------------------------------------------------------------------------
// Scratch (device globals — no allocations allowed)
// ---------------------------------------------------------------------------
__device__ __align__(256) float g_Q[(size_t)B_ * H_ * T_ * D_];
__device__ __align__(256) float g_K[(size_t)B_ * H_ * T_ * D_];
__device__ __align__(256) float g_V[(size_t)B_ * H_ * T_ * D_];
__device__ __align__(256) float g_cos[T_ * 64];
__device__ __align__(256) float g_sin[T_ * 64];
// pre-split bf16 hi/lo operands ([row][k] K-major, K = 2048)
__device__ __align__(256) __nv_bfloat16 g_xh[(size_t)MROWS * C_];
__device__ __align__(256) __nv_bfloat16 g_xl[(size_t)MROWS * C_];
__device__ __align__(256) __nv_bfloat16 g_wah[(size_t)NQKV_ * C_];
__device__ __align__(256) __nv_bfloat16 g_wal[(size_t)NQKV_ * C_];
__device__ __align__(256) __nv_bfloat16 g_wph[(size_t)C_ * C_];
__device__ __align__(256) __nv_bfloat16 g_wpl[(size_t)C_ * C_];
__device__ __align__(256) __nv_bfloat16 g_Yh[(size_t)MROWS * C_];
__device__ __align__(256) __nv_bfloat16 g_Yl[(size_t)MROWS * C_];

// ---------------------------------------------------------------------------
// helpers
// ---------------------------------------------------------------------------
__device__ __forceinline__ uint32_t smem_u32(const void* p) {
    uint32_t a;
    asm("{ .reg .u64 t; cvta.to.shared.u64 t, %1; cvt.u32.u64 %0, t; }" : "=r"(a) : "l"(p));
    return a;
}

#define CP_ASYNC16(dst, src) \
    asm volatile("cp.async.cg.shared.global [%0], [%1], 16;" :: "r"(dst), "l"(src) : "memory")
#define CP_COMMIT() asm volatile("cp.async.commit_group;" ::: "memory")
#define CP_WAIT1()  asm volatile("cp.async.wait_group 1;" ::: "memory")
#define CP_WAIT0()  asm volatile("cp.async.wait_group 0;" ::: "memory")

__device__ __forceinline__ void split_pair(float x0, float x1, unsigned& h, unsigned& l) {
    __nv_bfloat16 h0 = __float2bfloat16_rn(x0);
    __nv_bfloat16 h1 = __float2bfloat16_rn(x1);
    __nv_bfloat16 l0 = __float2bfloat16_rn(x0 - __bfloat162float(h0));
    __nv_bfloat16 l1 = __float2bfloat16_rn(x1 - __bfloat162float(h1));
    __nv_bfloat162 hh = __halves2bfloat162(h0, h1);
    __nv_bfloat162 ll = __halves2bfloat162(l0, l1);
    h = *reinterpret_cast<unsigned*>(&hh);
    l = *reinterpret_cast<unsigned*>(&ll);
}

__device__ __forceinline__ void mma_bf16(float c[4], const unsigned a[4], const unsigned b[2]) {
    asm volatile(
        "mma.sync.aligned.m16n8k16.row.col.f32.bf16.bf16.f32 "
        "{%0,%1,%2,%3}, {%4,%5,%6,%7}, {%8,%9}, {%0,%1,%2,%3};"
        : "+f"(c[0]), "+f"(c[1]), "+f"(c[2]), "+f"(c[3])
        : "r"(a[0]), "r"(a[1]), "r"(a[2]), "r"(a[3]), "r"(b[0]), "r"(b[1]));
}
__device__ __forceinline__ void mma_3x(float c[4],
                                       const unsigned ah[4], const unsigned al[4],
                                       const unsigned bh[2], const unsigned bl[2]) {
    mma_bf16(c, ah, bl);
    mma_bf16(c, al, bh);
    mma_bf16(c, ah, bh);
}

// ---------------------------------------------------------------------------
// Preprocessing kernels
// ---------------------------------------------------------------------------
__global__ void rope_table_kernel() {
    int i = blockIdx.x * blockDim.x + threadIdx.x;
    if (i >= T_ * 64) return;
    int t = i >> 6, d = i & 63;
    float invf = powf(10000.0f, -(float)d / 64.0f);
    float ang = (float)t * invf;
    g_cos[i] = (float)cos((double)ang);
    g_sin[i] = (float)sin((double)ang);
}

__global__ void rope_apply_kernel() {
    int i = blockIdx.x * blockDim.x + threadIdx.x;
    const int total = B_ * H_ * T_ * 64;
    if (i >= total) return;
    int d  = i & 63;
    int t  = (i >> 6) & (T_ - 1);
    int bh = i >> 17;
    size_t base = ((size_t)bh * T_ + t) * D_;
    float c = g_cos[(t << 6) + d];
    float s = g_sin[(t << 6) + d];
    const float scale = 0.08838834764831845f;  // 1/sqrt(128)
    float q1 = g_Q[base + d], q2 = g_Q[base + d + 64];
    g_Q[base + d]      = (q1 * c - q2 * s) * scale;
    g_Q[base + d + 64] = (q2 * c + q1 * s) * scale;
    float k1 = g_K[base + d], k2 = g_K[base + d + 64];
    g_K[base + d]      = k1 * c - k2 * s;
    g_K[base + d + 64] = k2 * c + k1 * s;
}

// x -> (hi, lo) bf16 (device-resolved outputs)
__global__ void split_x_kernel(const float* __restrict__ X, int n4) {
    int i = blockIdx.x * blockDim.x + threadIdx.x;
    if (i >= n4) return;
    float4 v = ((const float4*)X)[i];
    unsigned h01, l01, h23, l23;
    split_pair(v.x, v.y, h01, l01);
    split_pair(v.z, v.w, h23, l23);
    ((uint2*)g_xh)[i] = make_uint2(h01, h23);
    ((uint2*)g_xl)[i] = make_uint2(l01, l23);
}

// W[K][N] -> Wh/Wl[N][K] (transpose + split); device-resolved outputs.
template <int WSEL>
__global__ void split_wT_kernel(const float* __restrict__ W) {
    __nv_bfloat16* __restrict__ Wh = (WSEL == 1) ? g_wah : g_wph;
    __nv_bfloat16* __restrict__ Wl = (WSEL == 1) ? g_wal : g_wpl;
    const int K = C_;
    const int N = (WSEL == 1) ? NQKV_ : C_;

    __shared__ float tile[32][33];
    int nb = blockIdx.x * 32, kb = blockIdx.y * 32;
    int tx = threadIdx.x & 31, ty = threadIdx.x >> 5;
#pragma unroll
    for (int r = 0; r < 32; r += 8)
        tile[ty + r][tx] = W[(size_t)(kb + ty + r) * N + nb + tx];
    __syncthreads();
#pragma unroll
    for (int r = 0; r < 32; r += 8) {
        float v = tile[tx][ty + r];
        __nv_bfloat16 h = __float2bfloat16_rn(v);
        __nv_bfloat16 l = __float2bfloat16_rn(v - __bfloat162float(h));
        size_t o = (size_t)(nb + ty + r) * K + kb + tx;
        Wh[o] = h; Wl[o] = l;
    }
}

// ---------------------------------------------------------------------------
// bf16x3 GEMM — r11 structure (BK=64, all cp.async, 2-stage, 1 CTA/SM) plus
// explicit fragment double-buffering: slice ks+16's LDS issue while slice
// ks's HMMAs execute (removes exposed LDS latency in the MMA stream).
// Tile 128x128, 256 threads, warp tile 32x64.
// MODE 1: A=g_xh/l, B=g_wah/l, epilogue scatters Q/K/V.
// MODE 2: A=g_Yh/l, B=g_wph/l, epilogue plain fp32 write.
// ---------------------------------------------------------------------------
#define GBM 128
#define GBN 128
#define GBK 64                        // halves per k-tile
#define GST 72                        // padded k-stride (halves)
#define GTILE (128 * GST)             // 9216 halves
#define STAGE_H (4 * GTILE)           // Ah, Al, Bh, Bl
#define GEMM_SMEM_BYTES (2 * STAGE_H * 2)   // 147456
#define NKT 32                        // 2048 / 64

__device__ __forceinline__ void store_qkv(int r, int c, float val) {
    int b = r >> 11, t = r & 2047;
    int sec = c >> 11, cc = c & 2047;
    int h = cc >> 7, d = cc & 127;
    size_t dst = (((size_t)(b * H_ + h)) * T_ + t) * D_ + d;
    if (sec == 0)      g_Q[dst] = val;
    else if (sec == 1) g_K[dst] = val;
    else               g_V[dst] = val;
}

template <int MODE>
__global__ void __launch_bounds__(256) gemm_bf16x3_kernel(float* __restrict__ Cout) {
    extern __shared__ __align__(16) __nv_bfloat16 smg[];
    const uint32_t sbase = smem_u32(smg);

    const __nv_bfloat16* __restrict__ Ah_g = (MODE == 1) ? g_xh  : g_Yh;
    const __nv_bfloat16* __restrict__ Al_g = (MODE == 1) ? g_xl  : g_Yl;
    const __nv_bfloat16* __restrict__ Bh_g = (MODE == 1) ? g_wah : g_wph;
    const __nv_bfloat16* __restrict__ Bl_g = (MODE == 1) ? g_wal : g_wpl;

    const int tid = threadIdx.x;
    const int lane = tid & 31, warp = tid >> 5;
    const int warpM = warp >> 1, warpN = warp & 1;
    const int gid = lane >> 2, t4 = lane & 3;
    const int bm = blockIdx.y * GBM, bn = blockIdx.x * GBN;

    float acc[2][8][4];
#pragma unroll
    for (int mi = 0; mi < 2; mi++)
#pragma unroll
        for (int ni = 0; ni < 8; ni++)
#pragma unroll
            for (int q = 0; q < 4; q++) acc[mi][ni][q] = 0.f;

    // loader: per tile 1024 16B-chunks; chunk v: row = v>>3, kc = (v&7)*8 halves
#define ISSUE_STAGE(s, kt) do {                                                   \
    const int kof = (kt) * GBK;                                                   \
    _Pragma("unroll")                                                             \
    for (int i = 0; i < 4; i++) {                                                 \
        int v = tid + i * 256;                                                    \
        int row = v >> 3, kc = (v & 7) * 8;                                       \
        uint32_t dbase = sbase + (uint32_t)((s) * STAGE_H + row * GST + kc) * 2;  \
        size_t srcA = (size_t)(bm + row) * 2048 + kof + kc;                       \
        size_t srcB = (size_t)(bn + row) * 2048 + kof + kc;                       \
        CP_ASYNC16(dbase + 0u * (GTILE * 2), Ah_g + srcA);                        \
        CP_ASYNC16(dbase + 1u * (GTILE * 2), Al_g + srcA);                        \
        CP_ASYNC16(dbase + 2u * (GTILE * 2), Bh_g + srcB);                        \
        CP_ASYNC16(dbase + 3u * (GTILE * 2), Bl_g + srcB);                        \
    }                                                                             \
    CP_COMMIT();                                                                  \
} while (0)

    ISSUE_STAGE(0, 0);
    ISSUE_STAGE(1, 1);

    for (int kt = 0; kt < NKT; kt++) {
        const int cur = kt & 1;
        if (kt < NKT - 2) { CP_WAIT1(); } else { CP_WAIT0(); }
        __syncthreads();

        {
            const __nv_bfloat16* Ah = smg + cur * STAGE_H;
            const __nv_bfloat16* Al = Ah + GTILE;
            const __nv_bfloat16* Bh = Al + GTILE;
            const __nv_bfloat16* Bl = Bh + GTILE;

            // fragment double buffers
            unsigned fah[2][2][4], fal[2][2][4], fbh[2][8][2], fbl[2][8][2];

#define LOAD_FRAGS(f, ksv) do {                                                   \
    int ko = (ksv) + 2 * t4;                                                      \
    _Pragma("unroll")                                                             \
    for (int mi = 0; mi < 2; mi++) {                                              \
        int r0 = warpM * 32 + mi * 16 + gid;                                      \
        fah[f][mi][0] = *(const unsigned*)&Ah[r0 * GST + ko];                     \
        fah[f][mi][1] = *(const unsigned*)&Ah[(r0 + 8) * GST + ko];               \
        fah[f][mi][2] = *(const unsigned*)&Ah[r0 * GST + ko + 8];                 \
        fah[f][mi][3] = *(const unsigned*)&Ah[(r0 + 8) * GST + ko + 8];           \
        fal[f][mi][0] = *(const unsigned*)&Al[r0 * GST + ko];                     \
        fal[f][mi][1] = *(const unsigned*)&Al[(r0 + 8) * GST + ko];               \
        fal[f][mi][2] = *(const unsigned*)&Al[r0 * GST + ko + 8];                 \
        fal[f][mi][3] = *(const unsigned*)&Al[(r0 + 8) * GST + ko + 8];           \
    }                                                                             \
    _Pragma("unroll")                                                             \
    for (int ni = 0; ni < 8; ni++) {                                              \
        int nc = warpN * 64 + ni * 8 + gid;                                       \
        fbh[f][ni][0] = *(const unsigned*)&Bh[nc * GST + ko];                     \
        fbh[f][ni][1] = *(const unsigned*)&Bh[nc * GST + ko + 8];                 \
        fbl[f][ni][0] = *(const unsigned*)&Bl[nc * GST + ko];                     \
        fbl[f][ni][1] = *(const unsigned*)&Bl[nc * GST + ko + 8];                 \
    }                                                                             \
} while (0)

            LOAD_FRAGS(0, 0);
#pragma unroll
            for (int ks = 0; ks < GBK; ks += 16) {
                const int cf = (ks >> 4) & 1;
                if (ks + 16 < GBK) LOAD_FRAGS(cf ^ 1, ks + 16);
#pragma unroll
                for (int ni = 0; ni < 8; ni++)
#pragma unroll
                    for (int mi = 0; mi < 2; mi++)
                        mma_3x(acc[mi][ni], fah[cf][mi], fal[cf][mi],
                               fbh[cf][ni], fbl[cf][ni]);
            }
#undef LOAD_FRAGS
        }
        __syncthreads();
        if (kt + 2 < NKT) ISSUE_STAGE(cur, kt + 2);
    }
#undef ISSUE_STAGE

    // epilogue
#pragma unroll
    for (int mi = 0; mi < 2; mi++) {
#pragma unroll
        for (int ni = 0; ni < 8; ni++) {
            int r0 = bm + warpM * 32 + mi * 16 + gid;
            int c0 = bn + warpN * 64 + ni * 8 + t4 * 2;
            if (MODE == 1) {
                store_qkv(r0,     c0,     acc[mi][ni][0]);
                store_qkv(r0,     c0 + 1, acc[mi][ni][1]);
                store_qkv(r0 + 8, c0,     acc[mi][ni][2]);
                store_qkv(r0 + 8, c0 + 1, acc[mi][ni][3]);
            } else {
                Cout[(size_t)r0 * C_ + c0]           = acc[mi][ni][0];
                Cout[(size_t)r0 * C_ + c0 + 1]       = acc[mi][ni][1];
                Cout[(size_t)(r0 + 8) * C_ + c0]     = acc[mi][ni][2];
                Cout[(size_t)(r0 + 8) * C_ + c0 + 1] = acc[mi][ni][3];
            }
        }
    }
}

// ---------------------------------------------------------------------------
// Flash attention, causal, bf16x3 (round-2 verbatim compute).
// Epilogue writes pre-split Y (bf16 hi/lo) for the proj GEMM (r7-validated).
// ---------------------------------------------------------------------------
#define AQS 136
#define AVS 72
#define O_QH 0
#define O_QL (O_QH + 128 * AQS)
#define O_KH (O_QL + 128 * AQS)
#define O_KL (O_KH + 64 * AQS)
#define O_VTH (O_KL + 64 * AQS)
#define O_VTL (O_VTH + 128 * AVS)
#define O_PH (O_VTL + 128 * AVS)
#define O_PL (O_PH + 128 * AVS)
#define ATT_SMEM_HALVES (O_PL + 128 * AVS)
#define ATT_SMEM_BYTES (ATT_SMEM_HALVES * 2)

__global__ void __launch_bounds__(256) attn_kernel() {
    extern __shared__ __align__(16) __nv_bfloat16 sa[];
    __nv_bfloat16* Qh  = sa + O_QH;
    __nv_bfloat16* Ql  = sa + O_QL;
    __nv_bfloat16* Kh  = sa + O_KH;
    __nv_bfloat16* Kl  = sa + O_KL;
    __nv_bfloat16* VTh = sa + O_VTH;
    __nv_bfloat16* VTl = sa + O_VTL;
    __nv_bfloat16* Ph  = sa + O_PH;
    __nv_bfloat16* Pl  = sa + O_PL;

    const int tid = threadIdx.x;
    const int lane = tid & 31, w = tid >> 5;
    const int gid = lane >> 2, t4 = lane & 3;
    const int qtile = blockIdx.x, bh = blockIdx.y;
    const int qbase = qtile * 128;

    const float* Qg = g_Q + ((size_t)bh * T_ + qbase) * D_;
    const float* Kg = g_K + (size_t)bh * T_ * D_;
    const float* Vg = g_V + (size_t)bh * T_ * D_;

#pragma unroll
    for (int i = 0; i < 16; i++) {
        int u = tid + i * 256;
        int row = u >> 5, c4 = (u & 31) << 2;
        float4 v = *(const float4*)(Qg + (size_t)row * D_ + c4);
        unsigned h01, l01, h23, l23;
        split_pair(v.x, v.y, h01, l01);
        split_pair(v.z, v.w, h23, l23);
        *(unsigned*)&Qh[row * AQS + c4]     = h01;
        *(unsigned*)&Qh[row * AQS + c4 + 2] = h23;
        *(unsigned*)&Ql[row * AQS + c4]     = l01;
        *(unsigned*)&Ql[row * AQS + c4 + 2] = l23;
    }

    float o[16][4];
#pragma unroll
    for (int a = 0; a < 16; a++)
#pragma unroll
        for (int c = 0; c < 4; c++) o[a][c] = 0.f;
    float m0 = -1e30f, m1 = -1e30f, l0 = 0.f, l1 = 0.f;

    const int mrow = w * 16;
    const int rl0 = mrow + gid, rl1 = mrow + gid + 8;
    const int njt = 2 * qtile + 2;

    for (int j = 0; j < njt; j++) {
        __syncthreads();
#pragma unroll
        for (int i = 0; i < 8; i++) {
            int u = tid + i * 256;
            int row = u >> 5, c4 = (u & 31) << 2;
            float4 kv = *(const float4*)(Kg + ((size_t)j * 64 + row) * D_ + c4);
            unsigned h01, l01, h23, l23;
            split_pair(kv.x, kv.y, h01, l01);
            split_pair(kv.z, kv.w, h23, l23);
            *(unsigned*)&Kh[row * AQS + c4]     = h01;
            *(unsigned*)&Kh[row * AQS + c4 + 2] = h23;
            *(unsigned*)&Kl[row * AQS + c4]     = l01;
            *(unsigned*)&Kl[row * AQS + c4 + 2] = l23;
        }
#pragma unroll
        for (int i = 0; i < 8; i++) {
            int u = tid + i * 256;
            int d = u & 127, k0 = (u >> 7) << 2;
            float v0 = Vg[((size_t)j * 64 + k0)     * D_ + d];
            float v1 = Vg[((size_t)j * 64 + k0 + 1) * D_ + d];
            float v2 = Vg[((size_t)j * 64 + k0 + 2) * D_ + d];
            float v3 = Vg[((size_t)j * 64 + k0 + 3) * D_ + d];
            unsigned h01, l01, h23, l23;
            split_pair(v0, v1, h01, l01);
            split_pair(v2, v3, h23, l23);
            *(unsigned*)&VTh[d * AVS + k0]     = h01;
            *(unsigned*)&VTh[d * AVS + k0 + 2] = h23;
            *(unsigned*)&VTl[d * AVS + k0]     = l01;
            *(unsigned*)&VTl[d * AVS + k0 + 2] = l23;
        }
        __syncthreads();

        float s[8][4];
#pragma unroll
        for (int ni = 0; ni < 8; ni++)
#pragma unroll
            for (int q = 0; q < 4; q++) s[ni][q] = 0.f;

#pragma unroll
        for (int ks = 0; ks < 128; ks += 16) {
            int ko = ks + 2 * t4;
            unsigned ah[4], al[4];
            ah[0] = *(const unsigned*)&Qh[rl0 * AQS + ko];
            ah[1] = *(const unsigned*)&Qh[rl1 * AQS + ko];
            ah[2] = *(const unsigned*)&Qh[rl0 * AQS + ko + 8];
            ah[3] = *(const unsigned*)&Qh[rl1 * AQS + ko + 8];
            al[0] = *(const unsigned*)&Ql[rl0 * AQS + ko];
            al[1] = *(const unsigned*)&Ql[rl1 * AQS + ko];
            al[2] = *(const unsigned*)&Ql[rl0 * AQS + ko + 8];
            al[3] = *(const unsigned*)&Ql[rl1 * AQS + ko + 8];
#pragma unroll
            for (int ni = 0; ni < 8; ni++) {
                int nc = ni * 8 + gid;
                unsigned bhf[2], blf[2];
                bhf[0] = *(const unsigned*)&Kh[nc * AQS + ko];
                bhf[1] = *(const unsigned*)&Kh[nc * AQS + ko + 8];
                blf[0] = *(const unsigned*)&Kl[nc * AQS + ko];
                blf[1] = *(const unsigned*)&Kl[nc * AQS + ko + 8];
                mma_3x(s[ni], ah, al, bhf, blf);
            }
        }

        if (j >= 2 * qtile) {
            const int rg0 = qbase + rl0, rg1 = qbase + rl1;
#pragma unroll
            for (int ni = 0; ni < 8; ni++) {
                int cg = j * 64 + ni * 8 + t4 * 2;
                if (cg     > rg0) s[ni][0] = -1e30f;
                if (cg + 1 > rg0) s[ni][1] = -1e30f;
                if (cg     > rg1) s[ni][2] = -1e30f;
                if (cg + 1 > rg1) s[ni][3] = -1e30f;
            }
        }

        float rmax0 = -1e30f, rmax1 = -1e30f;
#pragma unroll
        for (int ni = 0; ni < 8; ni++) {
            rmax0 = fmaxf(rmax0, fmaxf(s[ni][0], s[ni][1]));
            rmax1 = fmaxf(rmax1, fmaxf(s[ni][2], s[ni][3]));
        }
        rmax0 = fmaxf(rmax0, __shfl_xor_sync(0xffffffffu, rmax0, 1));
        rmax0 = fmaxf(rmax0, __shfl_xor_sync(0xffffffffu, rmax0, 2));
        rmax1 = fmaxf(rmax1, __shfl_xor_sync(0xffffffffu, rmax1, 1));
        rmax1 = fmaxf(rmax1, __shfl_xor_sync(0xffffffffu, rmax1, 2));

        float nm0 = fmaxf(m0, rmax0), nm1 = fmaxf(m1, rmax1);
        float a0 = __expf(m0 - nm0), a1 = __expf(m1 - nm1);
        m0 = nm0; m1 = nm1;

        float sum0 = 0.f, sum1 = 0.f;
#pragma unroll
        for (int ni = 0; ni < 8; ni++) {
            s[ni][0] = __expf(s[ni][0] - nm0);
            s[ni][1] = __expf(s[ni][1] - nm0);
            s[ni][2] = __expf(s[ni][2] - nm1);
            s[ni][3] = __expf(s[ni][3] - nm1);
            sum0 += s[ni][0] + s[ni][1];
            sum1 += s[ni][2] + s[ni][3];
        }
        sum0 += __shfl_xor_sync(0xffffffffu, sum0, 1);
        sum0 += __shfl_xor_sync(0xffffffffu, sum0, 2);
        sum1 += __shfl_xor_sync(0xffffffffu, sum1, 1);
        sum1 += __shfl_xor_sync(0xffffffffu, sum1, 2);
        l0 = l0 * a0 + sum0;
        l1 = l1 * a1 + sum1;

#pragma unroll
        for (int di = 0; di < 16; di++) {
            o[di][0] *= a0; o[di][1] *= a0;
            o[di][2] *= a1; o[di][3] *= a1;
        }

#pragma unroll
        for (int ni = 0; ni < 8; ni++) {
            int cc = ni * 8 + 2 * t4;
            unsigned h01, lo01, h23, lo23;
            split_pair(s[ni][0], s[ni][1], h01, lo01);
            split_pair(s[ni][2], s[ni][3], h23, lo23);
            *(unsigned*)&Ph[rl0 * AVS + cc] = h01;
            *(unsigned*)&Pl[rl0 * AVS + cc] = lo01;
            *(unsigned*)&Ph[rl1 * AVS + cc] = h23;
            *(unsigned*)&Pl[rl1 * AVS + cc] = lo23;
        }
        __syncwarp();

#pragma unroll
        for (int kk = 0; kk < 64; kk += 16) {
            int ko = kk + 2 * t4;
            unsigned ah[4], al[4];
            ah[0] = *(const unsigned*)&Ph[rl0 * AVS + ko];
            ah[1] = *(const unsigned*)&Ph[rl1 * AVS + ko];
            ah[2] = *(const unsigned*)&Ph[rl0 * AVS + ko + 8];
            ah[3] = *(const unsigned*)&Ph[rl1 * AVS + ko + 8];
            al[0] = *(const unsigned*)&Pl[rl0 * AVS + ko];
            al[1] = *(const unsigned*)&Pl[rl1 * AVS + ko];
            al[2] = *(const unsigned*)&Pl[rl0 * AVS + ko + 8];
            al[3] = *(const unsigned*)&Pl[rl1 * AVS + ko + 8];
#pragma unroll
            for (int di = 0; di < 16; di++) {
                int nc = di * 8 + gid;
                unsigned bhf[2], blf[2];
                bhf[0] = *(const unsigned*)&VTh[nc * AVS + ko];
                bhf[1] = *(const unsigned*)&VTh[nc * AVS + ko + 8];
                blf[0] = *(const unsigned*)&VTl[nc * AVS + ko];
                blf[1] = *(const unsigned*)&VTl[nc * AVS + ko + 8];
                mma_3x(o[di], ah, al, bhf, blf);
            }
        }
        __syncwarp();
    }

    // Normalize + write pre-split Y (bf16 hi/lo) for the proj GEMM
    float il0 = 1.0f / l0, il1 = 1.0f / l1;
    int b = bh >> 4, h = bh & 15;
    int rg0 = qbase + rl0, rg1 = qbase + rl1;
#pragma unroll
    for (int di = 0; di < 16; di++) {
        size_t base0 = ((size_t)b * T_ + rg0) * C_ + h * D_ + di * 8 + t4 * 2;
        size_t base1 = ((size_t)b * T_ + rg1) * C_ + h * D_ + di * 8 + t4 * 2;
        unsigned hh, ll;
        split_pair(o[di][0] * il0, o[di][1] * il0, hh, ll);
        *(unsigned*)&g_Yh[base0] = hh;
        *(unsigned*)&g_Yl[base0] = ll;
        split_pair(o[di][2] * il1, o[di][3] * il1, hh, ll);
        *(unsigned*)&g_Yh[base1] = hh;
        *(unsigned*)&g_Yl[base1] = ll;
    }
}

// ---------------------------------------------------------------------------
// Launch
// ---------------------------------------------------------------------------
extern "C" void kernel_launch(void* const* d_in, const int* in_sizes, int n_in,
                              void* d_out, int out_size) {
    const float* x      = (const float*)d_in[0];
    const float* w_attn = (const float*)d_in[1];
    const float* w_proj = (const float*)d_in[2];
    float* out = (float*)d_out;
    (void)in_sizes; (void)n_in; (void)out_size;

    cudaFuncSetAttribute(attn_kernel, cudaFuncAttributeMaxDynamicSharedMemorySize,
                         ATT_SMEM_BYTES);
    cudaFuncSetAttribute(gemm_bf16x3_kernel<1>,
                         cudaFuncAttributeMaxDynamicSharedMemorySize, GEMM_SMEM_BYTES);
    cudaFuncSetAttribute(gemm_bf16x3_kernel<2>,
                         cudaFuncAttributeMaxDynamicSharedMemorySize, GEMM_SMEM_BYTES);

    // preprocessing: tables + pre-split operands (device-resolved outputs)
    rope_table_kernel<<<(T_ * 64 + 255) / 256, 256>>>();
    split_x_kernel<<<(MROWS * C_ / 4 + 255) / 256, 256>>>(x, MROWS * C_ / 4);
    split_wT_kernel<1><<<dim3(NQKV_ / 32, C_ / 32), 256>>>(w_attn);
    split_wT_kernel<2><<<dim3(C_ / 32, C_ / 32), 256>>>(w_proj);

    // QKV GEMM -> g_Q/K/V ([B,H,T,D] fp32)
    gemm_bf16x3_kernel<1><<<dim3(NQKV_ / GBN, MROWS / GBM), 256, GEMM_SMEM_BYTES>>>(nullptr);

    // RoPE + scale fold
    rope_apply_kernel<<<(B_ * H_ * T_ * 64 + 255) / 256, 256>>>();

    // attention -> g_Yh/g_Yl
    attn_kernel<<<dim3(T_ / 128, B_ * H_), 256, ATT_SMEM_BYTES>>>();

    // out projection -> d_out
    gemm_bf16x3_kernel<2><<<dim3(C_ / GBN, MROWS / GBM), 256, GEMM_SMEM_BYTES>>>(out);
}